// round 13
// baseline (speedup 1.0000x reference)
#include <cuda_runtime.h>
#include <cuda_bf16.h>
#include <cstdint>

#define GV 1024
#define GB 128
#define NN (GB * GV)          // 131072 columns (channel-major)
#define KORD 5
#define CKP 960               // padded K stride for split weights

// ---------------- scratch (device globals; no allocation) ----------------
__device__ float g_acta[(size_t)192 * NN];   // activation ping
__device__ float g_actb[(size_t)192 * NN];   // activation pong
__device__ float g_bn_s[192];
__device__ float g_bn_t[192];
__device__ double g_dsum[192];
__device__ double g_dsq[192];
__device__ __nv_bfloat16 g_wh[192 * CKP];    // W hi plane [F][960]
__device__ __nv_bfloat16 g_wl[192 * CKP];    // W lo plane [F][960]

// ---------------- helpers ----------------
__device__ __forceinline__ uint32_t smem_u32(const void* p) {
    uint32_t a;
    asm("{ .reg .u64 t; cvta.to.shared.u64 t, %1; cvt.u32.u64 %0, t; }" : "=r"(a) : "l"(p));
    return a;
}

__device__ __forceinline__ void mma_bf16(float* d, const uint32_t* a, const uint32_t* b) {
    asm volatile(
        "mma.sync.aligned.m16n8k16.row.col.f32.bf16.bf16.f32 "
        "{%0,%1,%2,%3}, {%4,%5,%6,%7}, {%8,%9}, {%0,%1,%2,%3};"
        : "+f"(d[0]), "+f"(d[1]), "+f"(d[2]), "+f"(d[3])
        : "r"(a[0]), "r"(a[1]), "r"(a[2]), "r"(a[3]), "r"(b[0]), "r"(b[1]));
}

#define LDSM_X4(r0, r1, r2, r3, addr) \
    asm volatile("ldmatrix.sync.aligned.m8n8.x4.shared.b16 {%0,%1,%2,%3}, [%4];" \
                 : "=r"(r0), "=r"(r1), "=r"(r2), "=r"(r3) : "r"(addr))
#define LDSM_X4T(r0, r1, r2, r3, addr) \
    asm volatile("ldmatrix.sync.aligned.m8n8.x4.trans.shared.b16 {%0,%1,%2,%3}, [%4];" \
                 : "=r"(r0), "=r"(r1), "=r"(r2), "=r"(r3) : "r"(addr))

#define CP_ASYNC16(dst, src) \
    asm volatile("cp.async.ca.shared.global [%0], [%1], 16;" :: "r"(dst), "l"(src) : "memory")
#define CP_COMMIT() asm volatile("cp.async.commit_group;" ::: "memory")
#define CP_WAIT0()  asm volatile("cp.async.wait_group 0;" ::: "memory")
#define STS16(addr, v) \
    asm volatile("st.shared.b16 [%0], %1;" :: "r"(addr), "h"(v))

// ---------------- W split + BN finalize (prev layer) + accumulator zeroing ----------------
__global__ void wsplit_bn(const float* __restrict__ W, int F, int CK,
                          const float* __restrict__ gamma_p, const float* __restrict__ beta_p,
                          int Fprev, int do_bn) {
    int idx = blockIdx.x * 256 + threadIdx.x;
    if (blockIdx.x == 0 && threadIdx.x < 192) {
        int f = threadIdx.x;
        if (do_bn && f < Fprev) {
            double mean = g_dsum[f] / (double)NN;
            double var  = g_dsq[f] / (double)NN - mean * mean;
            float sc = gamma_p[f] * rsqrtf((float)var + 1e-5f);
            g_bn_s[f] = sc;
            g_bn_t[f] = beta_p[f] - (float)mean * sc;
        }
        g_dsum[f] = 0.0;
        g_dsq[f]  = 0.0;
    }
    if (idx >= F * CKP) return;
    int k = idx % CKP;
    int f = idx / CKP;
    float v = (k < CK) ? W[(size_t)f * CK + k] : 0.f;
    __nv_bfloat16 h = __float2bfloat16_rn(v);
    g_wh[idx] = h;
    g_wl[idx] = __float2bfloat16_rn(v - __bfloat162float(h));
}

__device__ __forceinline__ float rsd_of(int i, int j) {
    int deg = (i > 0) + (i < 31) + (j > 0) + (j < 31);
    return (deg == 4) ? 0.5f : (deg == 3 ? 0.57735026918962576f : 0.70710678118654752f);
}

// ---------------- fused cheb+GEMM, warp-specialized ----------------
// 512 threads: warps 0-7 consumers (MMA, 96m x 128n), warps 8-15 producers
// (B generation via stencil recursion + A cp.async prefetch).
// Both A and B double-buffered; one __syncthreads per stage.
#define ROWA 176                       // 80 k * 2B + 16 pad
#define APL (96 * ROWA)                // 16896 per A plane
#define ABUF (2 * APL)                 // 33792 per A buffer (hi+lo)
#define OFF_B (2 * ABUF)               // 67584
#define ROWB2 272                      // 128 n * 2B + 16 pad
#define BPL (80 * ROWB2)               // 21760 per B plane
#define BBUF (2 * BPL)                 // 43520 per B buffer (hi+lo)
#define SMEMG (OFF_B + 2 * BBUF)       // 154624

__global__ void __launch_bounds__(512, 1)
gemm_fused(const float* __restrict__ in, float* __restrict__ out,
           int C, int F, int layer0) {
    extern __shared__ char smem[];
    const uint32_t sb = smem_u32(smem);

    const int tid  = threadIdx.x;
    const int lane = tid & 31;
    const int wid  = tid >> 5;
    const bool consumer = wid < 8;
    const int wm   = wid & 1;
    const int wn   = (wid >> 1) & 3;
    const int g    = lane >> 2;
    const int t4   = lane & 3;
    const int l15  = lane & 15;
    const int lhi  = lane >> 4;
    const int j    = lane;              // grid column (producers)
    const int pw   = wid - 8;           // producer warp id 0..7
    const int ptid = tid - 256;         // producer thread id 0..255

    const int m0 = blockIdx.x * 96;
    const int by = blockIdx.y;
    const int b  = by >> 3;             // batch
    const int i0 = (by & 7) * 4;        // first grid row of tile
    const int ns = (C + 15) >> 4;

    float acc[3][4][4];
#pragma unroll
    for (int a = 0; a < 3; a++)
#pragma unroll
        for (int bq = 0; bq < 4; bq++)
#pragma unroll
            for (int c = 0; c < 4; c++) acc[a][bq][c] = 0.f;

    // ---- producer: stencil weights (grid-invariant, hoisted) ----
    float rsv[12];
    if (!consumer) {
#pragma unroll
        for (int r = 0; r < 12; r++) {
            int iw = i0 - 4 + r;
            rsv[r] = (iw >= 0 && iw < 32) ? rsd_of(iw, j) : 0.f;
        }
    }

    // ---- A loader (producers: 256 threads, 1920 chunks/stage) ----
    auto load_A = [&](int s) {
        uint32_t dst = sb + (uint32_t)(s & 1) * ABUF;
        int k0 = s * 80;
#pragma unroll
        for (int i = 0; i < 8; i++) {
            int e = ptid + 256 * i;
            if (e < 1920) {
                int p = e >= 960;
                int id = e - 960 * p;
                int r = id / 10, q = id - 10 * r;
                const __nv_bfloat16* src =
                    (p ? g_wl : g_wh) + (size_t)(m0 + r) * CKP + k0 + q * 8;
                CP_ASYNC16(dst + p * APL + r * ROWA + q * 16, src);
            }
        }
        CP_COMMIT();
    };

    // ---- stencil: o = L~ t; rsv==0 keeps off-grid rows identically 0 ----
    auto stencil = [&](float* o, const float* t) {
        float z[12];
#pragma unroll
        for (int r = 0; r < 12; r++) z[r] = rsv[r] * t[r];
#pragma unroll
        for (int r = 0; r < 12; r++) {
            float a = 0.f;
            if (r > 0)  a += z[r - 1];
            if (r < 11) a += z[r + 1];
            float zl = __shfl_up_sync(0xffffffffu, z[r], 1);
            float zr = __shfl_down_sync(0xffffffffu, z[r], 1);
            a += (j > 0 ? zl : 0.f) + (j < 31 ? zr : 0.f);
            o[r] = -rsv[r] * a;
        }
    };

    auto store_k = [&](uint32_t bbase, int cl, int k, const float* a) {
        int rowB = cl * 5 + k;
        uint32_t base = bbase + rowB * ROWB2 + j * 2;
#pragma unroll
        for (int r = 4; r < 8; r++) {
            float v = a[r];
            __nv_bfloat16 h = __float2bfloat16_rn(v);
            __nv_bfloat16 lo = __float2bfloat16_rn(v - __bfloat162float(h));
            uint32_t addr = base + (r - 4) * 64;
            STS16(addr, (uint16_t)__bfloat16_as_ushort(h));
            STS16(addr + BPL, (uint16_t)__bfloat16_as_ushort(lo));
        }
    };

    // ---- B generator: producer warp pw does channels 2*pw, 2*pw+1 ----
    auto gen_B = [&](int s) {
        uint32_t bbase = sb + OFF_B + (uint32_t)(s & 1) * BBUF;
        int c0 = s * 16;
#pragma unroll
        for (int cc = 0; cc < 2; cc++) {
            int cl = pw * 2 + cc;
            int c  = c0 + cl;
            float tp[12], tc[12];
#pragma unroll
            for (int r = 0; r < 12; r++) {
                int iw = i0 - 4 + r;
                bool ok = (iw >= 0) && (iw < 32) && (c < C);
                float xv = 0.f;
                if (ok) {
                    if (layer0) {
                        xv = in[((size_t)b * C + c) * GV + iw * 32 + j];
                    } else {
                        float a = in[(size_t)c * NN + (size_t)b * GV + iw * 32 + j];
                        xv = fmaxf(fmaf(a, g_bn_s[c], g_bn_t[c]), 0.f);
                    }
                }
                tp[r] = xv;
            }
            store_k(bbase, cl, 0, tp);
            stencil(tc, tp);              // T1 = L T0
            store_k(bbase, cl, 1, tc);
#pragma unroll
            for (int k = 2; k < KORD; k++) {
                float lc[12];
                stencil(lc, tc);
                float tn[12];
#pragma unroll
                for (int r = 0; r < 12; r++) tn[r] = fmaf(2.f, lc[r], -tp[r]);
                store_k(bbase, cl, k, tn);
#pragma unroll
                for (int r = 0; r < 12; r++) { tp[r] = tc[r]; tc[r] = tn[r]; }
            }
        }
    };

    // ---- prologue: producers build A(0), B(0) ----
    if (!consumer) {
        load_A(0);
        gen_B(0);
        CP_WAIT0();
    }
    __syncthreads();

    // ---- main loop: consumers mma(s) || producers build (s+1) ----
    for (int s = 0; s < ns; s++) {
        if (!consumer) {
            if (s + 1 < ns) {
                load_A(s + 1);
                gen_B(s + 1);
            }
            CP_WAIT0();
        } else {
            const uint32_t abh = sb + (uint32_t)(s & 1) * ABUF;
            const uint32_t bbh = sb + OFF_B + (uint32_t)(s & 1) * BBUF;
#pragma unroll
            for (int q = 0; q < 5; q++) {
                uint32_t ah[3][4], al[3][4];
#pragma unroll
                for (int mf = 0; mf < 3; mf++) {
                    int row = wm * 48 + mf * 16 + l15;
                    uint32_t qa = (uint32_t)(2 * q + lhi);
                    uint32_t addr = abh + row * ROWA + qa * 16;
                    LDSM_X4(ah[mf][0], ah[mf][1], ah[mf][2], ah[mf][3], addr);
                    LDSM_X4(al[mf][0], al[mf][1], al[mf][2], al[mf][3], addr + APL);
                }
                uint32_t bh[2][4], bl[2][4];
#pragma unroll
                for (int p = 0; p < 2; p++) {
                    int krow = 16 * q + l15;
                    int nbyte = wn * 64 + p * 32 + lhi * 16;
                    uint32_t addr = bbh + krow * ROWB2 + nbyte;
                    LDSM_X4T(bh[p][0], bh[p][1], bh[p][2], bh[p][3], addr);
                    LDSM_X4T(bl[p][0], bl[p][1], bl[p][2], bl[p][3], addr + BPL);
                }
#pragma unroll
                for (int p = 0; p < 2; p++)
#pragma unroll
                    for (int h = 0; h < 2; h++) {
                        int nf = 2 * p + h;
#pragma unroll
                        for (int mf = 0; mf < 3; mf++) {
                            mma_bf16(acc[mf][nf], ah[mf], &bh[p][2 * h]);
                            mma_bf16(acc[mf][nf], al[mf], &bh[p][2 * h]);
                            mma_bf16(acc[mf][nf], ah[mf], &bl[p][2 * h]);
                        }
                    }
            }
        }
        __syncthreads();
    }

    // ---- epilogue 1: consumer fragments -> out ----
    const int n0 = by * 128;
    if (consumer) {
#pragma unroll
        for (int mf = 0; mf < 3; mf++) {
            int mrow = m0 + wm * 48 + mf * 16 + g;
#pragma unroll
            for (int nf = 0; nf < 4; nf++) {
                int col = n0 + wn * 32 + nf * 8 + 2 * t4;
                *(float2*)(out + (size_t)mrow * NN + col) =
                    make_float2(acc[mf][nf][0], acc[mf][nf][1]);
                *(float2*)(out + (size_t)(mrow + 8) * NN + col) =
                    make_float2(acc[mf][nf][2], acc[mf][nf][3]);
            }
        }
    }

    // ---- epilogue 2: fused BN partial stats (consumers compute, tid<96 reduces) ----
    float* reds = (float*)smem;          // [96][4]
    float* redq = (float*)smem + 384;    // [96][4]
    if (consumer) {
#pragma unroll
        for (int mf = 0; mf < 3; mf++) {
#pragma unroll
            for (int half = 0; half < 2; half++) {
                float s = 0.f, q = 0.f;
#pragma unroll
                for (int nf = 0; nf < 4; nf++) {
                    float v0f = acc[mf][nf][2 * half];
                    float v1f = acc[mf][nf][2 * half + 1];
                    s += v0f + v1f;
                    q += v0f * v0f + v1f * v1f;
                }
                s += __shfl_xor_sync(0xffffffffu, s, 1);
                s += __shfl_xor_sync(0xffffffffu, s, 2);
                q += __shfl_xor_sync(0xffffffffu, q, 1);
                q += __shfl_xor_sync(0xffffffffu, q, 2);
                if (t4 == 0) {
                    int row = wm * 48 + mf * 16 + half * 8 + g;
                    reds[row * 4 + wn] = s;
                    redq[row * 4 + wn] = q;
                }
            }
        }
    }
    __syncthreads();
    if (tid < 96) {
        float s = reds[tid * 4] + reds[tid * 4 + 1] + reds[tid * 4 + 2] + reds[tid * 4 + 3];
        float q = redq[tid * 4] + redq[tid * 4 + 1] + redq[tid * 4 + 2] + redq[tid * 4 + 3];
        atomicAdd(&g_dsum[m0 + tid], (double)s);
        atomicAdd(&g_dsq[m0 + tid],  (double)q);
    }
}

// ---------------- BN finalize (last layer only) ----------------
__global__ void bn_final(const float* __restrict__ gamma, const float* __restrict__ beta, int F) {
    int f = threadIdx.x;
    if (f >= F) return;
    double mean = g_dsum[f] / (double)NN;
    double var  = g_dsq[f] / (double)NN - mean * mean;
    float sc = gamma[f] * rsqrtf((float)var + 1e-5f);
    g_bn_s[f] = sc;
    g_bn_t[f] = beta[f] - (float)mean * sc;
}

// ---------------- classifier ----------------
__global__ void classifier(const float* __restrict__ act,
                           const float* __restrict__ cw, const float* __restrict__ cb,
                           float* __restrict__ out) {
    const int b0   = blockIdx.x * 4;
    const int lane = threadIdx.x & 31;
    const int warp = threadIdx.x >> 5;

    float acc[4][10];
#pragma unroll
    for (int bb = 0; bb < 4; bb++)
#pragma unroll
        for (int o = 0; o < 10; o++) acc[bb][o] = 0.f;

    const int NF = 96 * GV;
    for (int f = threadIdx.x; f < NF; f += 256) {
        int c = f >> 10, v = f & (GV - 1);
        float sc = g_bn_s[c], sh = g_bn_t[c];
        float w[10];
#pragma unroll
        for (int o = 0; o < 10; o++) w[o] = cw[(size_t)o * NF + f];
#pragma unroll
        for (int bb = 0; bb < 4; bb++) {
            float y = act[(size_t)c * NN + (size_t)(b0 + bb) * GV + v];
            float h = fmaxf(fmaf(y, sc, sh), 0.f);
#pragma unroll
            for (int o = 0; o < 10; o++) acc[bb][o] = fmaf(h, w[o], acc[bb][o]);
        }
    }

    __shared__ float part[8][40];
#pragma unroll
    for (int bb = 0; bb < 4; bb++)
#pragma unroll
        for (int o = 0; o < 10; o++) {
            float vsum = acc[bb][o];
#pragma unroll
            for (int off = 16; off > 0; off >>= 1)
                vsum += __shfl_down_sync(0xffffffffu, vsum, off);
            if (lane == 0) part[warp][bb * 10 + o] = vsum;
        }
    __syncthreads();
    if (threadIdx.x < 40) {
        float ssum = 0.f;
#pragma unroll
        for (int wq = 0; wq < 8; wq++) ssum += part[wq][threadIdx.x];
        int bb = threadIdx.x / 10, o = threadIdx.x % 10;
        out[(b0 + bb) * 10 + o] = ssum + cb[o];
    }
}

// ---------------- launch ----------------
extern "C" void kernel_launch(void* const* d_in, const int* in_sizes, int n_in,
                              void* d_out, int out_size) {
    (void)out_size;
    const float* x = (const float*)d_in[0];
    const float* w[7];
    const float* gg[7];
    const float* bb[7];

    if (n_in >= 25 && in_sizes[3] == 96) {  // dict order (w,g,b per layer)
        for (int i = 0; i < 7; i++) {
            w[i]  = (const float*)d_in[2 + 3 * i];
            gg[i] = (const float*)d_in[3 + 3 * i];
            bb[i] = (const float*)d_in[4 + 3 * i];
        }
    } else {                                // signature order
        for (int i = 0; i < 7; i++) {
            w[i]  = (const float*)d_in[2 + i];
            gg[i] = (const float*)d_in[9 + i];
            bb[i] = (const float*)d_in[16 + i];
        }
    }
    const float* clf_w = (const float*)d_in[23];
    const float* clf_b = (const float*)d_in[24];

    static int smem_set = 0;
    if (!smem_set) {
        cudaFuncSetAttribute(gemm_fused, cudaFuncAttributeMaxDynamicSharedMemorySize, SMEMG);
        smem_set = 1;
    }

    float *pa = nullptr, *pb = nullptr;
    cudaGetSymbolAddress((void**)&pa, g_acta);
    cudaGetSymbolAddress((void**)&pb, g_actb);

    const int CIN[7]  = {3, 96, 96, 96, 192, 192, 192};
    const int FOUT[7] = {96, 96, 96, 192, 192, 192, 96};

    for (int l = 0; l < 7; l++) {
        const int C = CIN[l], F = FOUT[l], CK = C * KORD;

        wsplit_bn<<<(F * CKP + 255) / 256, 256>>>(
            w[l], F, CK,
            l ? gg[l - 1] : nullptr, l ? bb[l - 1] : nullptr,
            l ? FOUT[l - 1] : 0, l ? 1 : 0);

        const float* src = (l == 0) ? x : (((l - 1) & 1) ? pb : pa);
        float* dst = (l & 1) ? pb : pa;

        dim3 grid(F / 96, NN / 128);
        gemm_fused<<<grid, 512, SMEMG>>>(src, dst, C, F, l == 0 ? 1 : 0);
    }

    bn_final<<<1, 192>>>(gg[6], bb[6], 96);
    classifier<<<32, 256>>>(pa, clf_w, clf_b, (float*)d_out);
}

// round 15
// speedup vs baseline: 1.2346x; 1.2346x over previous
#include <cuda_runtime.h>
#include <cuda_bf16.h>
#include <cstdint>

#define GV 1024
#define GB 128
#define NN (GB * GV)          // 131072 columns (channel-major)
#define KORD 5
#define CKP 960               // padded K stride for split weights

// ---------------- scratch (device globals; no allocation) ----------------
__device__ __nv_bfloat16 g_fkh[(size_t)960 * NN];  // Fk hi plane [CK][NN]
__device__ __nv_bfloat16 g_fkl[(size_t)960 * NN];  // Fk lo plane [CK][NN]
__device__ float g_act[(size_t)192 * NN];          // conv output Y [F][NN] fp32
__device__ float g_bn_s[192];
__device__ float g_bn_t[192];
__device__ double g_dsum[192];
__device__ double g_dsq[192];
__device__ __nv_bfloat16 g_wh[192 * CKP];          // W hi plane [F][960]
__device__ __nv_bfloat16 g_wl[192 * CKP];          // W lo plane [F][960]

// ---------------- helpers ----------------
__device__ __forceinline__ uint32_t smem_u32(const void* p) {
    uint32_t a;
    asm("{ .reg .u64 t; cvta.to.shared.u64 t, %1; cvt.u32.u64 %0, t; }" : "=r"(a) : "l"(p));
    return a;
}

__device__ __forceinline__ void mma_bf16(float* d, const uint32_t* a, const uint32_t* b) {
    asm volatile(
        "mma.sync.aligned.m16n8k16.row.col.f32.bf16.bf16.f32 "
        "{%0,%1,%2,%3}, {%4,%5,%6,%7}, {%8,%9}, {%0,%1,%2,%3};"
        : "+f"(d[0]), "+f"(d[1]), "+f"(d[2]), "+f"(d[3])
        : "r"(a[0]), "r"(a[1]), "r"(a[2]), "r"(a[3]), "r"(b[0]), "r"(b[1]));
}

#define LDSM_X4(r0, r1, r2, r3, addr) \
    asm volatile("ldmatrix.sync.aligned.m8n8.x4.shared.b16 {%0,%1,%2,%3}, [%4];" \
                 : "=r"(r0), "=r"(r1), "=r"(r2), "=r"(r3) : "r"(addr))
#define LDSM_X4T(r0, r1, r2, r3, addr) \
    asm volatile("ldmatrix.sync.aligned.m8n8.x4.trans.shared.b16 {%0,%1,%2,%3}, [%4];" \
                 : "=r"(r0), "=r"(r1), "=r"(r2), "=r"(r3) : "r"(addr))

#define CP_ASYNC16(dst, src) \
    asm volatile("cp.async.ca.shared.global [%0], [%1], 16;" :: "r"(dst), "l"(src) : "memory")
#define CP_COMMIT() asm volatile("cp.async.commit_group;" ::: "memory")
#define CP_WAIT0()  asm volatile("cp.async.wait_group 0;" ::: "memory")

// ---------------- W split + BN finalize (prev layer) + accumulator zeroing ----------------
__global__ void wsplit_bn(const float* __restrict__ W, int F, int CK,
                          const float* __restrict__ gamma_p, const float* __restrict__ beta_p,
                          int Fprev, int do_bn) {
    int idx = blockIdx.x * 256 + threadIdx.x;
    if (blockIdx.x == 0 && threadIdx.x < 192) {
        int f = threadIdx.x;
        if (do_bn && f < Fprev) {
            double mean = g_dsum[f] / (double)NN;
            double var  = g_dsq[f] / (double)NN - mean * mean;
            float sc = gamma_p[f] * rsqrtf((float)var + 1e-5f);
            g_bn_s[f] = sc;
            g_bn_t[f] = beta_p[f] - (float)mean * sc;
        }
        g_dsum[f] = 0.0;
        g_dsq[f]  = 0.0;
    }
    if (idx >= F * CKP) return;
    int k = idx % CKP;
    int f = idx / CKP;
    float v = (k < CK) ? W[(size_t)f * CK + k] : 0.f;
    __nv_bfloat16 h = __float2bfloat16_rn(v);
    g_wh[idx] = h;
    g_wl[idx] = __float2bfloat16_rn(v - __bfloat162float(h));
}

// ---------------- Chebyshev expansion, writes bf16 hi/lo planes ----------------
__device__ __forceinline__ float rsd_of(int i, int j) {
    int deg = (i > 0) + (i < 31) + (j > 0) + (j < 31);
    return (deg == 4) ? 0.5f : (deg == 3 ? 0.57735026918962576f : 0.70710678118654752f);
}

__device__ __forceinline__ void store_split(size_t idx, float x) {
    __nv_bfloat16 h = __float2bfloat16_rn(x);
    g_fkh[idx] = h;
    g_fkl[idx] = __float2bfloat16_rn(x - __bfloat162float(h));
}

__global__ void cheb_expand(const float* __restrict__ xin, int C, int layer0) {
    __shared__ float s[GV];
    const int v = threadIdx.x;
    const int c = blockIdx.x;
    const int b = blockIdx.y;
    const int i = v >> 5, j = v & 31;

    float x;
    if (layer0) {
        x = xin[((size_t)b * C + c) * GV + v];
    } else {
        x = g_act[(size_t)c * NN + (size_t)b * GV + v];
        x = fmaxf(fmaf(x, g_bn_s[c], g_bn_t[c]), 0.0f);
    }

    const float rv = rsd_of(i, j);
    const float w_up = (i > 0)  ? rv * rsd_of(i - 1, j) : 0.f;
    const float w_dn = (i < 31) ? rv * rsd_of(i + 1, j) : 0.f;
    const float w_lf = (j > 0)  ? rv * rsd_of(i, j - 1) : 0.f;
    const float w_rt = (j < 31) ? rv * rsd_of(i, j + 1) : 0.f;
    const int up = (i > 0)  ? v - 32 : v;
    const int dn = (i < 31) ? v + 32 : v;
    const int lf = (j > 0)  ? v - 1  : v;
    const int rt = (j < 31) ? v + 1  : v;

    const size_t base = (size_t)(c * KORD) * NN + (size_t)b * GV + v;

    store_split(base, x);
    s[v] = x;
    __syncthreads();
    float t1 = -(w_up * s[up] + w_dn * s[dn] + w_lf * s[lf] + w_rt * s[rt]);
    store_split(base + NN, t1);

    float tp = x, tc = t1;
#pragma unroll
    for (int k = 2; k < KORD; k++) {
        __syncthreads();
        s[v] = tc;
        __syncthreads();
        float l = -(w_up * s[up] + w_dn * s[dn] + w_lf * s[lf] + w_rt * s[rt]);
        float tn = fmaf(2.0f, l, -tp);
        store_split(base + (size_t)k * NN, tn);
        tp = tc;
        tc = tn;
    }
}

// ---------------- tensor-core GEMM (mma.sync bf16 hi/lo 3-term) + fused BN stats ----
// Templated on BM (96 or 192): warp grid 2m x 4n, warp tile (BM/2)m x 32n, BK=32.
// smem/stage: Ah[BM][80B] Al[BM][80B] Bh[32][272B] Bl[32][272B]
#define ROWA 80
#define ROWBB 272
#define SZ_BP (32 * ROWBB)                 // 8704

template <int BM, int MF, int MINB>
__global__ void __launch_bounds__(256, MINB)
gemm_mma(int F, int CK) {
    constexpr int APL   = BM * ROWA;          // per A plane
    constexpr int OFF_B = 2 * APL;
    constexpr int STAGE = 2 * APL + 2 * SZ_BP;

    extern __shared__ char smem[];
    const uint32_t sbase = smem_u32(smem);

    const int tid  = threadIdx.x;
    const int lane = tid & 31;
    const int wid  = tid >> 5;
    const int wm   = wid & 1;        // 0..1  (m)
    const int wn   = wid >> 1;       // 0..3  (n)
    const int g    = lane >> 2;      // 0..7
    const int t4   = lane & 3;       // 0..3
    const int l15  = lane & 15;
    const int lhi  = lane >> 4;      // 0..1

    const int m0 = blockIdx.x * BM;
    const int n0 = blockIdx.y * 128;
    const int ns = (CK + 31) >> 5;

    float acc[MF][4][4];
#pragma unroll
    for (int a = 0; a < MF; a++)
#pragma unroll
        for (int b = 0; b < 4; b++)
#pragma unroll
            for (int c = 0; c < 4; c++) acc[a][b][c] = 0.f;

    // ---- async load of one stage (A: BM*8 chunks, B: 1024 chunks) ----
    auto load_stage = [&](uint32_t sdst, int k0) {
        constexpr int ACH = BM * 4;           // chunks per A plane
#pragma unroll
        for (int i = 0; i < (2 * ACH + 255) / 256; i++) {
            int e = tid + 256 * i;
            if (e < 2 * ACH) {
                int p = e >= ACH;
                int id = e - ACH * p;
                int r = id >> 2, q = id & 3;
                const __nv_bfloat16* src =
                    (p ? g_wl : g_wh) + (size_t)(m0 + r) * CKP + k0 + q * 8;
                CP_ASYNC16(sdst + p * APL + r * ROWA + q * 16, src);
            }
        }
#pragma unroll
        for (int i = 0; i < 4; i++) {         // B planes
            int e = tid + 256 * i;
            int p = e >= 512;
            int id = e - 512 * p;
            int k = id >> 4, cc = id & 15;
            const __nv_bfloat16* src = (p ? g_fkl : g_fkh) + (size_t)(k0 + k) * NN + n0 + cc * 8;
            CP_ASYNC16(sdst + OFF_B + p * SZ_BP + k * ROWBB + cc * 16, src);
        }
        CP_COMMIT();
    };

    load_stage(sbase, 0);
    CP_WAIT0();
    __syncthreads();

    for (int s = 0; s < ns; s++) {
        const uint32_t buf = sbase + (uint32_t)(s & 1) * STAGE;
        const bool more = (s + 1 < ns);
        if (more) load_stage(sbase + (uint32_t)((s + 1) & 1) * STAGE, (s + 1) * 32);

#pragma unroll
        for (int c = 0; c < 2; c++) {
            uint32_t ah[MF][4], al[MF][4];
#pragma unroll
            for (int mf = 0; mf < MF; mf++) {
                int row = wm * (BM / 2) + mf * 16 + l15;
                uint32_t qa = (uint32_t)(2 * c + lhi);
                uint32_t addr = buf + row * ROWA + qa * 16;
                LDSM_X4(ah[mf][0], ah[mf][1], ah[mf][2], ah[mf][3], addr);
                LDSM_X4(al[mf][0], al[mf][1], al[mf][2], al[mf][3], addr + APL);
            }
            uint32_t bh[2][4], bl[2][4];
#pragma unroll
            for (int p = 0; p < 2; p++) {
                int krow = 16 * c + l15;
                int nbyte = wn * 64 + p * 32 + lhi * 16;
                uint32_t addr = buf + OFF_B + krow * ROWBB + nbyte;
                LDSM_X4T(bh[p][0], bh[p][1], bh[p][2], bh[p][3], addr);
                LDSM_X4T(bl[p][0], bl[p][1], bl[p][2], bl[p][3], addr + SZ_BP);
            }
#pragma unroll
            for (int p = 0; p < 2; p++)
#pragma unroll
                for (int h = 0; h < 2; h++) {
                    int nf = 2 * p + h;
#pragma unroll
                    for (int mf = 0; mf < MF; mf++) {
                        mma_bf16(acc[mf][nf], ah[mf], &bh[p][2 * h]);
                        mma_bf16(acc[mf][nf], al[mf], &bh[p][2 * h]);
                        mma_bf16(acc[mf][nf], ah[mf], &bl[p][2 * h]);
                    }
                }
        }
        if (more) CP_WAIT0();   // drain ALL pending groups (next stage fully resident)
        __syncthreads();
    }

    // ---- epilogue 1: fragments -> g_act ----
#pragma unroll
    for (int mf = 0; mf < MF; mf++) {
        int mrow = m0 + wm * (BM / 2) + mf * 16 + g;
#pragma unroll
        for (int nf = 0; nf < 4; nf++) {
            int col = n0 + wn * 32 + nf * 8 + 2 * t4;
            *(float2*)(g_act + (size_t)mrow * NN + col) =
                make_float2(acc[mf][nf][0], acc[mf][nf][1]);
            *(float2*)(g_act + (size_t)(mrow + 8) * NN + col) =
                make_float2(acc[mf][nf][2], acc[mf][nf][3]);
        }
    }

    // ---- epilogue 2: fused BN partial stats ----
    float* reds = (float*)smem;              // [BM][4]
    float* redq = (float*)smem + BM * 4;     // [BM][4]
#pragma unroll
    for (int mf = 0; mf < MF; mf++) {
#pragma unroll
        for (int half = 0; half < 2; half++) {
            float s = 0.f, q = 0.f;
#pragma unroll
            for (int nf = 0; nf < 4; nf++) {
                float v0 = acc[mf][nf][2 * half];
                float v1 = acc[mf][nf][2 * half + 1];
                s += v0 + v1;
                q += v0 * v0 + v1 * v1;
            }
            s += __shfl_xor_sync(0xffffffffu, s, 1);
            s += __shfl_xor_sync(0xffffffffu, s, 2);
            q += __shfl_xor_sync(0xffffffffu, q, 1);
            q += __shfl_xor_sync(0xffffffffu, q, 2);
            if (t4 == 0) {
                int row = wm * (BM / 2) + mf * 16 + half * 8 + g;
                reds[row * 4 + wn] = s;
                redq[row * 4 + wn] = q;
            }
        }
    }
    __syncthreads();
    if (tid < BM) {
        float s = reds[tid * 4] + reds[tid * 4 + 1] + reds[tid * 4 + 2] + reds[tid * 4 + 3];
        float q = redq[tid * 4] + redq[tid * 4 + 1] + redq[tid * 4 + 2] + redq[tid * 4 + 3];
        atomicAdd(&g_dsum[m0 + tid], (double)s);
        atomicAdd(&g_dsq[m0 + tid],  (double)q);
    }
}

// ---------------- BN finalize (last layer only) ----------------
__global__ void bn_final(const float* __restrict__ gamma, const float* __restrict__ beta, int F) {
    int f = threadIdx.x;
    if (f >= F) return;
    double mean = g_dsum[f] / (double)NN;
    double var  = g_dsq[f] / (double)NN - mean * mean;
    float sc = gamma[f] * rsqrtf((float)var + 1e-5f);
    g_bn_s[f] = sc;
    g_bn_t[f] = beta[f] - (float)mean * sc;
}

// ---------------- classifier ----------------
__global__ void classifier(const float* __restrict__ cw, const float* __restrict__ cb,
                           float* __restrict__ out) {
    const int b0   = blockIdx.x * 4;
    const int lane = threadIdx.x & 31;
    const int warp = threadIdx.x >> 5;

    float acc[4][10];
#pragma unroll
    for (int bb = 0; bb < 4; bb++)
#pragma unroll
        for (int o = 0; o < 10; o++) acc[bb][o] = 0.f;

    const int NF = 96 * GV;
    for (int f = threadIdx.x; f < NF; f += 256) {
        int c = f >> 10, v = f & (GV - 1);
        float sc = g_bn_s[c], sh = g_bn_t[c];
        float w[10];
#pragma unroll
        for (int o = 0; o < 10; o++) w[o] = cw[(size_t)o * NF + f];
#pragma unroll
        for (int bb = 0; bb < 4; bb++) {
            float y = g_act[(size_t)c * NN + (size_t)(b0 + bb) * GV + v];
            float h = fmaxf(fmaf(y, sc, sh), 0.f);
#pragma unroll
            for (int o = 0; o < 10; o++) acc[bb][o] = fmaf(h, w[o], acc[bb][o]);
        }
    }

    __shared__ float part[8][40];
#pragma unroll
    for (int bb = 0; bb < 4; bb++)
#pragma unroll
        for (int o = 0; o < 10; o++) {
            float vsum = acc[bb][o];
#pragma unroll
            for (int off = 16; off > 0; off >>= 1)
                vsum += __shfl_down_sync(0xffffffffu, vsum, off);
            if (lane == 0) part[warp][bb * 10 + o] = vsum;
        }
    __syncthreads();
    if (threadIdx.x < 40) {
        float ssum = 0.f;
#pragma unroll
        for (int wq = 0; wq < 8; wq++) ssum += part[wq][threadIdx.x];
        int bb = threadIdx.x / 10, o = threadIdx.x % 10;
        out[(b0 + bb) * 10 + o] = ssum + cb[o];
    }
}

// ---------------- launch ----------------
extern "C" void kernel_launch(void* const* d_in, const int* in_sizes, int n_in,
                              void* d_out, int out_size) {
    (void)out_size;
    const float* x = (const float*)d_in[0];
    const float* w[7];
    const float* gg[7];
    const float* bb[7];

    if (n_in >= 25 && in_sizes[3] == 96) {  // dict order (w,g,b per layer)
        for (int i = 0; i < 7; i++) {
            w[i]  = (const float*)d_in[2 + 3 * i];
            gg[i] = (const float*)d_in[3 + 3 * i];
            bb[i] = (const float*)d_in[4 + 3 * i];
        }
    } else {                                // signature order
        for (int i = 0; i < 7; i++) {
            w[i]  = (const float*)d_in[2 + i];
            gg[i] = (const float*)d_in[9 + i];
            bb[i] = (const float*)d_in[16 + i];
        }
    }
    const float* clf_w = (const float*)d_in[23];
    const float* clf_b = (const float*)d_in[24];

    const int SM96  = 2 * (2 * 96 * ROWA + 2 * SZ_BP);    // 65536
    const int SM192 = 2 * (2 * 192 * ROWA + 2 * SZ_BP);   // 96256

    static int smem_set = 0;
    if (!smem_set) {
        cudaFuncSetAttribute(gemm_mma<96, 3, 2>,  cudaFuncAttributeMaxDynamicSharedMemorySize, SM96);
        cudaFuncSetAttribute(gemm_mma<192, 6, 1>, cudaFuncAttributeMaxDynamicSharedMemorySize, SM192);
        smem_set = 1;
    }

    const int CIN[7]  = {3, 96, 96, 96, 192, 192, 192};
    const int FOUT[7] = {96, 96, 96, 192, 192, 192, 96};

    for (int l = 0; l < 7; l++) {
        const int C = CIN[l], F = FOUT[l], CK = C * KORD;

        wsplit_bn<<<(F * CKP + 255) / 256, 256>>>(
            w[l], F, CK,
            l ? gg[l - 1] : nullptr, l ? bb[l - 1] : nullptr,
            l ? FOUT[l - 1] : 0, l ? 1 : 0);

        cheb_expand<<<dim3(C, GB), GV>>>(x, C, l == 0 ? 1 : 0);

        if (F == 96) {
            dim3 grid(1, NN / 128);
            gemm_mma<96, 3, 2><<<grid, 256, SM96>>>(F, CK);
        } else {
            dim3 grid(1, NN / 128);
            gemm_mma<192, 6, 1><<<grid, 256, SM192>>>(F, CK);
        }
    }

    bn_final<<<1, 192>>>(gg[6], bb[6], 96);
    classifier<<<32, 256>>>(clf_w, clf_b, (float*)d_out);
}

// round 16
// speedup vs baseline: 1.2728x; 1.0310x over previous
#include <cuda_runtime.h>
#include <cuda_bf16.h>
#include <cstdint>

#define GV 1024
#define GB 128
#define NN (GB * GV)          // 131072 columns (channel-major)
#define KORD 5
#define CKP 960               // padded K stride for split weights

// ---------------- scratch (device globals; no allocation) ----------------
__device__ __nv_bfloat16 g_fkh[(size_t)960 * NN];  // Fk hi plane [CK][NN]
__device__ __nv_bfloat16 g_fkl[(size_t)960 * NN];  // Fk lo plane [CK][NN]
__device__ float g_act[(size_t)192 * NN];          // conv output Y [F][NN] fp32
__device__ float g_bn_s[192];
__device__ float g_bn_t[192];
__device__ double g_dsum[192];
__device__ double g_dsq[192];
__device__ __nv_bfloat16 g_wh[192 * CKP];          // W hi plane [F][960]
__device__ __nv_bfloat16 g_wl[192 * CKP];          // W lo plane [F][960]

// ---------------- helpers ----------------
__device__ __forceinline__ uint32_t smem_u32(const void* p) {
    uint32_t a;
    asm("{ .reg .u64 t; cvta.to.shared.u64 t, %1; cvt.u32.u64 %0, t; }" : "=r"(a) : "l"(p));
    return a;
}

__device__ __forceinline__ void mma_bf16(float* d, const uint32_t* a, const uint32_t* b) {
    asm volatile(
        "mma.sync.aligned.m16n8k16.row.col.f32.bf16.bf16.f32 "
        "{%0,%1,%2,%3}, {%4,%5,%6,%7}, {%8,%9}, {%0,%1,%2,%3};"
        : "+f"(d[0]), "+f"(d[1]), "+f"(d[2]), "+f"(d[3])
        : "r"(a[0]), "r"(a[1]), "r"(a[2]), "r"(a[3]), "r"(b[0]), "r"(b[1]));
}

#define LDSM_X4(r0, r1, r2, r3, addr) \
    asm volatile("ldmatrix.sync.aligned.m8n8.x4.shared.b16 {%0,%1,%2,%3}, [%4];" \
                 : "=r"(r0), "=r"(r1), "=r"(r2), "=r"(r3) : "r"(addr))
#define LDSM_X4T(r0, r1, r2, r3, addr) \
    asm volatile("ldmatrix.sync.aligned.m8n8.x4.trans.shared.b16 {%0,%1,%2,%3}, [%4];" \
                 : "=r"(r0), "=r"(r1), "=r"(r2), "=r"(r3) : "r"(addr))

#define CP_ASYNC16(dst, src) \
    asm volatile("cp.async.ca.shared.global [%0], [%1], 16;" :: "r"(dst), "l"(src) : "memory")
#define CP_COMMIT() asm volatile("cp.async.commit_group;" ::: "memory")
#define CP_WAIT0()  asm volatile("cp.async.wait_group 0;" ::: "memory")
#define CP_WAIT1()  asm volatile("cp.async.wait_group 1;" ::: "memory")

// ---------------- W split + BN finalize (prev layer) + accumulator zeroing ----------------
__global__ void wsplit_bn(const float* __restrict__ W, int F, int CK,
                          const float* __restrict__ gamma_p, const float* __restrict__ beta_p,
                          int Fprev, int do_bn) {
    int idx = blockIdx.x * 256 + threadIdx.x;
    if (blockIdx.x == 0 && threadIdx.x < 192) {
        int f = threadIdx.x;
        if (do_bn && f < Fprev) {
            double mean = g_dsum[f] / (double)NN;
            double var  = g_dsq[f] / (double)NN - mean * mean;
            float sc = gamma_p[f] * rsqrtf((float)var + 1e-5f);
            g_bn_s[f] = sc;
            g_bn_t[f] = beta_p[f] - (float)mean * sc;
        }
        g_dsum[f] = 0.0;
        g_dsq[f]  = 0.0;
    }
    if (idx >= F * CKP) return;
    int k = idx % CKP;
    int f = idx / CKP;
    float v = (k < CK) ? W[(size_t)f * CK + k] : 0.f;
    __nv_bfloat16 h = __float2bfloat16_rn(v);
    g_wh[idx] = h;
    g_wl[idx] = __float2bfloat16_rn(v - __bfloat162float(h));
}

// ---------------- Chebyshev expansion, writes bf16 hi/lo planes ----------------
__device__ __forceinline__ float rsd_of(int i, int j) {
    int deg = (i > 0) + (i < 31) + (j > 0) + (j < 31);
    return (deg == 4) ? 0.5f : (deg == 3 ? 0.57735026918962576f : 0.70710678118654752f);
}

__device__ __forceinline__ void store_split(size_t idx, float x) {
    __nv_bfloat16 h = __float2bfloat16_rn(x);
    g_fkh[idx] = h;
    g_fkl[idx] = __float2bfloat16_rn(x - __bfloat162float(h));
}

__global__ void cheb_expand(const float* __restrict__ xin, int C, int layer0) {
    __shared__ float s[GV];
    const int v = threadIdx.x;
    const int c = blockIdx.x;
    const int b = blockIdx.y;
    const int i = v >> 5, j = v & 31;

    float x;
    if (layer0) {
        x = xin[((size_t)b * C + c) * GV + v];
    } else {
        x = g_act[(size_t)c * NN + (size_t)b * GV + v];
        x = fmaxf(fmaf(x, g_bn_s[c], g_bn_t[c]), 0.0f);
    }

    const float rv = rsd_of(i, j);
    const float w_up = (i > 0)  ? rv * rsd_of(i - 1, j) : 0.f;
    const float w_dn = (i < 31) ? rv * rsd_of(i + 1, j) : 0.f;
    const float w_lf = (j > 0)  ? rv * rsd_of(i, j - 1) : 0.f;
    const float w_rt = (j < 31) ? rv * rsd_of(i, j + 1) : 0.f;
    const int up = (i > 0)  ? v - 32 : v;
    const int dn = (i < 31) ? v + 32 : v;
    const int lf = (j > 0)  ? v - 1  : v;
    const int rt = (j < 31) ? v + 1  : v;

    const size_t base = (size_t)(c * KORD) * NN + (size_t)b * GV + v;

    store_split(base, x);
    s[v] = x;
    __syncthreads();
    float t1 = -(w_up * s[up] + w_dn * s[dn] + w_lf * s[lf] + w_rt * s[rt]);
    store_split(base + NN, t1);

    float tp = x, tc = t1;
#pragma unroll
    for (int k = 2; k < KORD; k++) {
        __syncthreads();
        s[v] = tc;
        __syncthreads();
        float l = -(w_up * s[up] + w_dn * s[dn] + w_lf * s[lf] + w_rt * s[rt]);
        float tn = fmaf(2.0f, l, -tp);
        store_split(base + (size_t)k * NN, tn);
        tp = tc;
        tc = tn;
    }
}

// ---------------- tensor-core GEMM (mma.sync bf16 hi/lo 3-term) + fused BN stats ----
// CTA: 96m x 128n, BK=32. 8 warps = 2(m) x 4(n); warp tile 48m x 32n.
// 3-stage cp.async ring: stage = Ah[96][80B] Al Bh[32][272B] Bl = 32768 B
#define ROWA 80
#define ROWBB 272
#define SZ_AP (96 * ROWA)                 // 7680
#define SZ_BP (32 * ROWBB)                // 8704
#define OFF_AH 0
#define OFF_AL SZ_AP
#define OFF_B  (2 * SZ_AP)
#define STAGE  (2 * SZ_AP + 2 * SZ_BP)    // 32768
#define SMEM_GEMM (3 * STAGE)             // 98304

__global__ void __launch_bounds__(256, 2)
gemm_mma(int F, int CK) {
    extern __shared__ char smem[];
    const uint32_t sbase = smem_u32(smem);

    const int tid  = threadIdx.x;
    const int lane = tid & 31;
    const int wid  = tid >> 5;
    const int wm   = wid & 1;        // 0..1  (m)
    const int wn   = wid >> 1;       // 0..3  (n)
    const int g    = lane >> 2;      // 0..7
    const int t4   = lane & 3;       // 0..3
    const int l15  = lane & 15;
    const int lhi  = lane >> 4;      // 0..1

    const int m0 = blockIdx.x * 96;
    const int n0 = blockIdx.y * 128;
    const int ns = (CK + 31) >> 5;

    float acc[3][4][4];
#pragma unroll
    for (int a = 0; a < 3; a++)
#pragma unroll
        for (int b = 0; b < 4; b++)
#pragma unroll
            for (int c = 0; c < 4; c++) acc[a][b][c] = 0.f;

    // ---- async load of one stage (A: 768 chunks, B: 1024 chunks) ----
    auto load_stage = [&](int s) {
        uint32_t sdst = sbase + (uint32_t)(s % 3) * STAGE;
        int k0 = s * 32;
#pragma unroll
        for (int i = 0; i < 3; i++) {              // A planes
            int e = tid + 256 * i;
            int p = e >= 384;
            int id = e - 384 * p;
            int r = id >> 2, q = id & 3;
            const __nv_bfloat16* src = (p ? g_wl : g_wh) + (size_t)(m0 + r) * CKP + k0 + q * 8;
            CP_ASYNC16(sdst + (p ? OFF_AL : OFF_AH) + r * ROWA + q * 16, src);
        }
#pragma unroll
        for (int i = 0; i < 4; i++) {              // B planes
            int e = tid + 256 * i;
            int p = e >= 512;
            int id = e - 512 * p;
            int k = id >> 4, cc = id & 15;
            const __nv_bfloat16* src = (p ? g_fkl : g_fkh) + (size_t)(k0 + k) * NN + n0 + cc * 8;
            CP_ASYNC16(sdst + OFF_B + p * SZ_BP + k * ROWBB + cc * 16, src);
        }
        CP_COMMIT();
    };

    // ---- prologue: 2 stages in flight ----
    load_stage(0);
    if (ns > 1) load_stage(1);

    for (int s = 0; s < ns; s++) {
        // loads through stage s complete; stage s+1 may remain in flight
        if (s + 1 < ns) { CP_WAIT1(); } else { CP_WAIT0(); }
        __syncthreads();   // all warps done with buf[(s) % 3]'s previous life + see load(s)

        if (s + 2 < ns) load_stage(s + 2);   // ring slot (s+2)%3 is free now

        const uint32_t buf = sbase + (uint32_t)(s % 3) * STAGE;
#pragma unroll
        for (int c = 0; c < 2; c++) {
            uint32_t ah[3][4], al[3][4];
#pragma unroll
            for (int mf = 0; mf < 3; mf++) {
                int row = wm * 48 + mf * 16 + l15;
                uint32_t qa = (uint32_t)(2 * c + lhi);
                uint32_t addr = buf + OFF_AH + row * ROWA + qa * 16;
                LDSM_X4(ah[mf][0], ah[mf][1], ah[mf][2], ah[mf][3], addr);
                LDSM_X4(al[mf][0], al[mf][1], al[mf][2], al[mf][3], addr + SZ_AP);
            }
            uint32_t bh[2][4], bl[2][4];
#pragma unroll
            for (int p = 0; p < 2; p++) {
                int krow = 16 * c + l15;
                int nbyte = wn * 64 + p * 32 + lhi * 16;
                uint32_t addr = buf + OFF_B + krow * ROWBB + nbyte;
                LDSM_X4T(bh[p][0], bh[p][1], bh[p][2], bh[p][3], addr);
                LDSM_X4T(bl[p][0], bl[p][1], bl[p][2], bl[p][3], addr + SZ_BP);
            }
#pragma unroll
            for (int p = 0; p < 2; p++)
#pragma unroll
                for (int h = 0; h < 2; h++) {
                    int nf = 2 * p + h;
#pragma unroll
                    for (int mf = 0; mf < 3; mf++) {
                        mma_bf16(acc[mf][nf], ah[mf], &bh[p][2 * h]);
                        mma_bf16(acc[mf][nf], al[mf], &bh[p][2 * h]);
                        mma_bf16(acc[mf][nf], ah[mf], &bl[p][2 * h]);
                    }
                }
        }
    }
    __syncthreads();

    // ---- epilogue 1: fragments -> g_act ----
#pragma unroll
    for (int mf = 0; mf < 3; mf++) {
        int mrow = m0 + wm * 48 + mf * 16 + g;
#pragma unroll
        for (int nf = 0; nf < 4; nf++) {
            int col = n0 + wn * 32 + nf * 8 + 2 * t4;
            *(float2*)(g_act + (size_t)mrow * NN + col) =
                make_float2(acc[mf][nf][0], acc[mf][nf][1]);
            *(float2*)(g_act + (size_t)(mrow + 8) * NN + col) =
                make_float2(acc[mf][nf][2], acc[mf][nf][3]);
        }
    }

    // ---- epilogue 2: fused BN partial stats ----
    float* reds = (float*)smem;          // [96][4]
    float* redq = (float*)smem + 384;    // [96][4]
#pragma unroll
    for (int mf = 0; mf < 3; mf++) {
#pragma unroll
        for (int half = 0; half < 2; half++) {
            float s = 0.f, q = 0.f;
#pragma unroll
            for (int nf = 0; nf < 4; nf++) {
                float v0 = acc[mf][nf][2 * half];
                float v1 = acc[mf][nf][2 * half + 1];
                s += v0 + v1;
                q += v0 * v0 + v1 * v1;
            }
            s += __shfl_xor_sync(0xffffffffu, s, 1);
            s += __shfl_xor_sync(0xffffffffu, s, 2);
            q += __shfl_xor_sync(0xffffffffu, q, 1);
            q += __shfl_xor_sync(0xffffffffu, q, 2);
            if (t4 == 0) {
                int row = wm * 48 + mf * 16 + half * 8 + g;
                reds[row * 4 + wn] = s;
                redq[row * 4 + wn] = q;
            }
        }
    }
    __syncthreads();
    if (tid < 96) {
        float s = reds[tid * 4] + reds[tid * 4 + 1] + reds[tid * 4 + 2] + reds[tid * 4 + 3];
        float q = redq[tid * 4] + redq[tid * 4 + 1] + redq[tid * 4 + 2] + redq[tid * 4 + 3];
        atomicAdd(&g_dsum[m0 + tid], (double)s);
        atomicAdd(&g_dsq[m0 + tid],  (double)q);
    }
}

// ---------------- BN finalize (last layer only) ----------------
__global__ void bn_final(const float* __restrict__ gamma, const float* __restrict__ beta, int F) {
    int f = threadIdx.x;
    if (f >= F) return;
    double mean = g_dsum[f] / (double)NN;
    double var  = g_dsq[f] / (double)NN - mean * mean;
    float sc = gamma[f] * rsqrtf((float)var + 1e-5f);
    g_bn_s[f] = sc;
    g_bn_t[f] = beta[f] - (float)mean * sc;
}

// ---------------- classifier ----------------
__global__ void classifier(const float* __restrict__ cw, const float* __restrict__ cb,
                           float* __restrict__ out) {
    const int b0   = blockIdx.x * 4;
    const int lane = threadIdx.x & 31;
    const int warp = threadIdx.x >> 5;

    float acc[4][10];
#pragma unroll
    for (int bb = 0; bb < 4; bb++)
#pragma unroll
        for (int o = 0; o < 10; o++) acc[bb][o] = 0.f;

    const int NF = 96 * GV;
    for (int f = threadIdx.x; f < NF; f += 256) {
        int c = f >> 10, v = f & (GV - 1);
        float sc = g_bn_s[c], sh = g_bn_t[c];
        float w[10];
#pragma unroll
        for (int o = 0; o < 10; o++) w[o] = cw[(size_t)o * NF + f];
#pragma unroll
        for (int bb = 0; bb < 4; bb++) {
            float y = g_act[(size_t)c * NN + (size_t)(b0 + bb) * GV + v];
            float h = fmaxf(fmaf(y, sc, sh), 0.f);
#pragma unroll
            for (int o = 0; o < 10; o++) acc[bb][o] = fmaf(h, w[o], acc[bb][o]);
        }
    }

    __shared__ float part[8][40];
#pragma unroll
    for (int bb = 0; bb < 4; bb++)
#pragma unroll
        for (int o = 0; o < 10; o++) {
            float vsum = acc[bb][o];
#pragma unroll
            for (int off = 16; off > 0; off >>= 1)
                vsum += __shfl_down_sync(0xffffffffu, vsum, off);
            if (lane == 0) part[warp][bb * 10 + o] = vsum;
        }
    __syncthreads();
    if (threadIdx.x < 40) {
        float ssum = 0.f;
#pragma unroll
        for (int wq = 0; wq < 8; wq++) ssum += part[wq][threadIdx.x];
        int bb = threadIdx.x / 10, o = threadIdx.x % 10;
        out[(b0 + bb) * 10 + o] = ssum + cb[o];
    }
}

// ---------------- launch ----------------
extern "C" void kernel_launch(void* const* d_in, const int* in_sizes, int n_in,
                              void* d_out, int out_size) {
    (void)out_size;
    const float* x = (const float*)d_in[0];
    const float* w[7];
    const float* gg[7];
    const float* bb[7];

    if (n_in >= 25 && in_sizes[3] == 96) {  // dict order (w,g,b per layer)
        for (int i = 0; i < 7; i++) {
            w[i]  = (const float*)d_in[2 + 3 * i];
            gg[i] = (const float*)d_in[3 + 3 * i];
            bb[i] = (const float*)d_in[4 + 3 * i];
        }
    } else {                                // signature order
        for (int i = 0; i < 7; i++) {
            w[i]  = (const float*)d_in[2 + i];
            gg[i] = (const float*)d_in[9 + i];
            bb[i] = (const float*)d_in[16 + i];
        }
    }
    const float* clf_w = (const float*)d_in[23];
    const float* clf_b = (const float*)d_in[24];

    static int smem_set = 0;
    if (!smem_set) {
        cudaFuncSetAttribute(gemm_mma, cudaFuncAttributeMaxDynamicSharedMemorySize, SMEM_GEMM);
        smem_set = 1;
    }

    const int CIN[7]  = {3, 96, 96, 96, 192, 192, 192};
    const int FOUT[7] = {96, 96, 96, 192, 192, 192, 96};

    for (int l = 0; l < 7; l++) {
        const int C = CIN[l], F = FOUT[l], CK = C * KORD;

        wsplit_bn<<<(F * CKP + 255) / 256, 256>>>(
            w[l], F, CK,
            l ? gg[l - 1] : nullptr, l ? bb[l - 1] : nullptr,
            l ? FOUT[l - 1] : 0, l ? 1 : 0);

        cheb_expand<<<dim3(C, GB), GV>>>(x, C, l == 0 ? 1 : 0);

        dim3 grid(F / 96, NN / 128);
        gemm_mma<<<grid, 256, SMEM_GEMM>>>(F, CK);
    }

    bn_final<<<1, 192>>>(gg[6], bb[6], 96);
    classifier<<<32, 256>>>(clf_w, clf_b, (float*)d_out);
}

// round 17
// speedup vs baseline: 1.5102x; 1.1864x over previous
#include <cuda_runtime.h>
#include <cuda_bf16.h>
#include <cstdint>

#define GV 1024
#define GB 128
#define NN (GB * GV)          // 131072 columns (channel-major)
#define KORD 5
#define CKP 960               // padded K stride for split weights

// ---------------- scratch (device globals; no allocation) ----------------
__device__ __nv_bfloat16 g_fkh[(size_t)960 * NN];  // Fk hi plane [CK][NN]
__device__ __nv_bfloat16 g_fkl[(size_t)960 * NN];  // Fk lo plane [CK][NN]
__device__ float g_act[(size_t)192 * NN];          // conv output Y [F][NN] fp32
__device__ float g_bn_s[192];
__device__ float g_bn_t[192];
__device__ double g_dsum[192];
__device__ double g_dsq[192];
__device__ __nv_bfloat16 g_wh[192 * CKP];          // W hi plane [F][960]
__device__ __nv_bfloat16 g_wl[192 * CKP];          // W lo plane [F][960]

// ---------------- helpers ----------------
__device__ __forceinline__ uint32_t smem_u32(const void* p) {
    uint32_t a;
    asm("{ .reg .u64 t; cvta.to.shared.u64 t, %1; cvt.u32.u64 %0, t; }" : "=r"(a) : "l"(p));
    return a;
}

__device__ __forceinline__ void mma_bf16(float* d, const uint32_t* a, const uint32_t* b) {
    asm volatile(
        "mma.sync.aligned.m16n8k16.row.col.f32.bf16.bf16.f32 "
        "{%0,%1,%2,%3}, {%4,%5,%6,%7}, {%8,%9}, {%0,%1,%2,%3};"
        : "+f"(d[0]), "+f"(d[1]), "+f"(d[2]), "+f"(d[3])
        : "r"(a[0]), "r"(a[1]), "r"(a[2]), "r"(a[3]), "r"(b[0]), "r"(b[1]));
}

#define LDSM_X4(r0, r1, r2, r3, addr) \
    asm volatile("ldmatrix.sync.aligned.m8n8.x4.shared.b16 {%0,%1,%2,%3}, [%4];" \
                 : "=r"(r0), "=r"(r1), "=r"(r2), "=r"(r3) : "r"(addr))
#define LDSM_X4T(r0, r1, r2, r3, addr) \
    asm volatile("ldmatrix.sync.aligned.m8n8.x4.trans.shared.b16 {%0,%1,%2,%3}, [%4];" \
                 : "=r"(r0), "=r"(r1), "=r"(r2), "=r"(r3) : "r"(addr))

#define CP_ASYNC16(dst, src) \
    asm volatile("cp.async.ca.shared.global [%0], [%1], 16;" :: "r"(dst), "l"(src) : "memory")
#define CP_COMMIT() asm volatile("cp.async.commit_group;" ::: "memory")
#define CP_WAIT0()  asm volatile("cp.async.wait_group 0;" ::: "memory")

// ---------------- W split + BN finalize (prev layer) + accumulator zeroing ----------------
__global__ void wsplit_bn(const float* __restrict__ W, int F, int CK,
                          const float* __restrict__ gamma_p, const float* __restrict__ beta_p,
                          int Fprev, int do_bn) {
    int idx = blockIdx.x * 256 + threadIdx.x;
    if (blockIdx.x == 0 && threadIdx.x < 192) {
        int f = threadIdx.x;
        if (do_bn && f < Fprev) {
            double mean = g_dsum[f] / (double)NN;
            double var  = g_dsq[f] / (double)NN - mean * mean;
            float sc = gamma_p[f] * rsqrtf((float)var + 1e-5f);
            g_bn_s[f] = sc;
            g_bn_t[f] = beta_p[f] - (float)mean * sc;
        }
        g_dsum[f] = 0.0;
        g_dsq[f]  = 0.0;
    }
    if (idx >= F * CKP) return;
    int k = idx % CKP;
    int f = idx / CKP;
    float v = (k < CK) ? W[(size_t)f * CK + k] : 0.f;
    __nv_bfloat16 h = __float2bfloat16_rn(v);
    g_wh[idx] = h;
    g_wl[idx] = __float2bfloat16_rn(v - __bfloat162float(h));
}

// ---------------- Chebyshev expansion, 4 columns per thread ----------------
__device__ __forceinline__ float rsd_of(int i, int j) {
    int deg = (i > 0) + (i < 31) + (j > 0) + (j < 31);
    return (deg == 4) ? 0.5f : (deg == 3 ? 0.57735026918962576f : 0.70710678118654752f);
}

__device__ __forceinline__ uint32_t pack_bf16(float a, float b) {
    __nv_bfloat16 ha = __float2bfloat16_rn(a), hb = __float2bfloat16_rn(b);
    return (uint32_t)__bfloat16_as_ushort(ha) | ((uint32_t)__bfloat16_as_ushort(hb) << 16);
}

__global__ void __launch_bounds__(256)
cheb_expand(const float* __restrict__ xin, int C, int layer0) {
    __shared__ float s[GV];
    const int t  = threadIdx.x;         // 0..255
    const int v0 = 4 * t;
    const int c  = blockIdx.x;
    const int b  = blockIdx.y;
    const int i  = v0 >> 5, j0 = v0 & 31;

    float x[4];
    if (layer0) {
        float4 xv = *(const float4*)&xin[((size_t)b * C + c) * GV + v0];
        x[0] = xv.x; x[1] = xv.y; x[2] = xv.z; x[3] = xv.w;
    } else {
        float4 xv = *(const float4*)&g_act[(size_t)c * NN + (size_t)b * GV + v0];
        float sc = g_bn_s[c], sh = g_bn_t[c];
        x[0] = fmaxf(fmaf(xv.x, sc, sh), 0.f);
        x[1] = fmaxf(fmaf(xv.y, sc, sh), 0.f);
        x[2] = fmaxf(fmaf(xv.z, sc, sh), 0.f);
        x[3] = fmaxf(fmaf(xv.w, sc, sh), 0.f);
    }

    float wup[4], wdn[4], wlf[4], wrt[4];
#pragma unroll
    for (int q = 0; q < 4; q++) {
        int j = j0 + q;
        float rv = rsd_of(i, j);
        wup[q] = (i > 0)  ? rv * rsd_of(i - 1, j) : 0.f;
        wdn[q] = (i < 31) ? rv * rsd_of(i + 1, j) : 0.f;
        wlf[q] = (j > 0)  ? rv * rsd_of(i, j - 1) : 0.f;
        wrt[q] = (j < 31) ? rv * rsd_of(i, j + 1) : 0.f;
    }
    const int up  = (i > 0)   ? v0 - 32 : v0;   // weight 0 guards validity
    const int dn  = (i < 31)  ? v0 + 32 : v0;
    const int lfi = (j0 > 0)  ? v0 - 1  : v0;
    const int rti = (j0 < 28) ? v0 + 4  : v0 + 3;

    const size_t obase = (size_t)(c * KORD) * NN + (size_t)b * GV + v0;

    auto stq = [&](int k, const float* a) {
        uint32_t hA = pack_bf16(a[0], a[1]);
        uint32_t hB = pack_bf16(a[2], a[3]);
        float r0 = a[0] - __bfloat162float(__float2bfloat16_rn(a[0]));
        float r1 = a[1] - __bfloat162float(__float2bfloat16_rn(a[1]));
        float r2 = a[2] - __bfloat162float(__float2bfloat16_rn(a[2]));
        float r3 = a[3] - __bfloat162float(__float2bfloat16_rn(a[3]));
        uint32_t lA = pack_bf16(r0, r1);
        uint32_t lB = pack_bf16(r2, r3);
        *(uint2*)&g_fkh[obase + (size_t)k * NN] = make_uint2(hA, hB);
        *(uint2*)&g_fkl[obase + (size_t)k * NN] = make_uint2(lA, lB);
    };

    // stencil: o = L~ tq, using smem for cross-thread neighbors, regs intra-quad
    auto sten = [&](float* o, const float* tq) {
        float sl = s[lfi];
        float sr = s[rti];
        o[0] = -(wup[0] * s[up + 0] + wdn[0] * s[dn + 0] + wlf[0] * sl    + wrt[0] * tq[1]);
        o[1] = -(wup[1] * s[up + 1] + wdn[1] * s[dn + 1] + wlf[1] * tq[0] + wrt[1] * tq[2]);
        o[2] = -(wup[2] * s[up + 2] + wdn[2] * s[dn + 2] + wlf[2] * tq[1] + wrt[2] * tq[3]);
        o[3] = -(wup[3] * s[up + 3] + wdn[3] * s[dn + 3] + wlf[3] * tq[2] + wrt[3] * sr);
    };

    stq(0, x);
    *(float4*)&s[v0] = make_float4(x[0], x[1], x[2], x[3]);
    __syncthreads();
    float t1[4];
    sten(t1, x);
    stq(1, t1);

    float tp[4] = {x[0], x[1], x[2], x[3]};
    float tc[4] = {t1[0], t1[1], t1[2], t1[3]};
#pragma unroll
    for (int k = 2; k < KORD; k++) {
        __syncthreads();
        *(float4*)&s[v0] = make_float4(tc[0], tc[1], tc[2], tc[3]);
        __syncthreads();
        float l[4];
        sten(l, tc);
        float tn[4];
#pragma unroll
        for (int q = 0; q < 4; q++) tn[q] = fmaf(2.0f, l[q], -tp[q]);
        stq(k, tn);
#pragma unroll
        for (int q = 0; q < 4; q++) { tp[q] = tc[q]; tc[q] = tn[q]; }
    }
}

// ---------------- tensor-core GEMM (mma.sync bf16 hi/lo 3-term) + fused BN stats ----
// CTA: 96m x 128n, BK=32. 8 warps = 2(m) x 4(n); warp tile 48m x 32n.
// 2-stage: stage = Ah[96][80B] Al Bh[32][272B] Bl = 32768 B
#define ROWA 80
#define ROWBB 272
#define SZ_AP (96 * ROWA)                 // 7680
#define SZ_BP (32 * ROWBB)                // 8704
#define OFF_AH 0
#define OFF_AL SZ_AP
#define OFF_B  (2 * SZ_AP)
#define STAGE  (2 * SZ_AP + 2 * SZ_BP)    // 32768
#define SMEM_GEMM (2 * STAGE)             // 65536

__global__ void __launch_bounds__(256, 2)
gemm_mma(int F, int CK) {
    extern __shared__ char smem[];
    const uint32_t sbase = smem_u32(smem);

    const int tid  = threadIdx.x;
    const int lane = tid & 31;
    const int wid  = tid >> 5;
    const int wm   = wid & 1;        // 0..1  (m)
    const int wn   = wid >> 1;       // 0..3  (n)
    const int g    = lane >> 2;      // 0..7
    const int t4   = lane & 3;       // 0..3
    const int l15  = lane & 15;
    const int lhi  = lane >> 4;      // 0..1

    const int m0 = blockIdx.x * 96;
    const int n0 = blockIdx.y * 128;
    const int ns = (CK + 31) >> 5;

    float acc[3][4][4];
#pragma unroll
    for (int a = 0; a < 3; a++)
#pragma unroll
        for (int b = 0; b < 4; b++)
#pragma unroll
            for (int c = 0; c < 4; c++) acc[a][b][c] = 0.f;

    // ---- async load of one stage (A: 768 chunks, B: 1024 chunks) ----
    auto load_stage = [&](uint32_t sdst, int k0) {
#pragma unroll
        for (int i = 0; i < 3; i++) {              // A planes
            int e = tid + 256 * i;
            int p = e >= 384;
            int id = e - 384 * p;
            int r = id >> 2, q = id & 3;
            const __nv_bfloat16* src = (p ? g_wl : g_wh) + (size_t)(m0 + r) * CKP + k0 + q * 8;
            CP_ASYNC16(sdst + (p ? OFF_AL : OFF_AH) + r * ROWA + q * 16, src);
        }
#pragma unroll
        for (int i = 0; i < 4; i++) {              // B planes
            int e = tid + 256 * i;
            int p = e >= 512;
            int id = e - 512 * p;
            int k = id >> 4, cc = id & 15;
            const __nv_bfloat16* src = (p ? g_fkl : g_fkh) + (size_t)(k0 + k) * NN + n0 + cc * 8;
            CP_ASYNC16(sdst + OFF_B + p * SZ_BP + k * ROWBB + cc * 16, src);
        }
        CP_COMMIT();
    };

    load_stage(sbase, 0);
    CP_WAIT0();
    __syncthreads();

    for (int s = 0; s < ns; s++) {
        const uint32_t buf = sbase + (uint32_t)(s & 1) * STAGE;
        const bool more = (s + 1 < ns);
        if (more) load_stage(sbase + (uint32_t)((s + 1) & 1) * STAGE, (s + 1) * 32);

#pragma unroll
        for (int c = 0; c < 2; c++) {
            uint32_t ah[3][4], al[3][4];
#pragma unroll
            for (int mf = 0; mf < 3; mf++) {
                int row = wm * 48 + mf * 16 + l15;
                uint32_t qa = (uint32_t)(2 * c + lhi);
                uint32_t addr = buf + OFF_AH + row * ROWA + qa * 16;
                LDSM_X4(ah[mf][0], ah[mf][1], ah[mf][2], ah[mf][3], addr);
                LDSM_X4(al[mf][0], al[mf][1], al[mf][2], al[mf][3], addr + SZ_AP);
            }
            uint32_t bh[2][4], bl[2][4];
#pragma unroll
            for (int p = 0; p < 2; p++) {
                int krow = 16 * c + l15;
                int nbyte = wn * 64 + p * 32 + lhi * 16;
                uint32_t addr = buf + OFF_B + krow * ROWBB + nbyte;
                LDSM_X4T(bh[p][0], bh[p][1], bh[p][2], bh[p][3], addr);
                LDSM_X4T(bl[p][0], bl[p][1], bl[p][2], bl[p][3], addr + SZ_BP);
            }
#pragma unroll
            for (int p = 0; p < 2; p++)
#pragma unroll
                for (int h = 0; h < 2; h++) {
                    int nf = 2 * p + h;
#pragma unroll
                    for (int mf = 0; mf < 3; mf++) {
                        mma_bf16(acc[mf][nf], ah[mf], &bh[p][2 * h]);
                        mma_bf16(acc[mf][nf], al[mf], &bh[p][2 * h]);
                        mma_bf16(acc[mf][nf], ah[mf], &bl[p][2 * h]);
                    }
                }
        }
        if (more) CP_WAIT0();
        __syncthreads();
    }

    // ---- epilogue 1: fragments -> g_act ----
#pragma unroll
    for (int mf = 0; mf < 3; mf++) {
        int mrow = m0 + wm * 48 + mf * 16 + g;
#pragma unroll
        for (int nf = 0; nf < 4; nf++) {
            int col = n0 + wn * 32 + nf * 8 + 2 * t4;
            *(float2*)(g_act + (size_t)mrow * NN + col) =
                make_float2(acc[mf][nf][0], acc[mf][nf][1]);
            *(float2*)(g_act + (size_t)(mrow + 8) * NN + col) =
                make_float2(acc[mf][nf][2], acc[mf][nf][3]);
        }
    }

    // ---- epilogue 2: fused BN partial stats ----
    float* reds = (float*)smem;          // [96][4]
    float* redq = (float*)smem + 384;    // [96][4]
#pragma unroll
    for (int mf = 0; mf < 3; mf++) {
#pragma unroll
        for (int half = 0; half < 2; half++) {
            float s = 0.f, q = 0.f;
#pragma unroll
            for (int nf = 0; nf < 4; nf++) {
                float v0 = acc[mf][nf][2 * half];
                float v1 = acc[mf][nf][2 * half + 1];
                s += v0 + v1;
                q += v0 * v0 + v1 * v1;
            }
            s += __shfl_xor_sync(0xffffffffu, s, 1);
            s += __shfl_xor_sync(0xffffffffu, s, 2);
            q += __shfl_xor_sync(0xffffffffu, q, 1);
            q += __shfl_xor_sync(0xffffffffu, q, 2);
            if (t4 == 0) {
                int row = wm * 48 + mf * 16 + half * 8 + g;
                reds[row * 4 + wn] = s;
                redq[row * 4 + wn] = q;
            }
        }
    }
    __syncthreads();
    if (tid < 96) {
        float s = reds[tid * 4] + reds[tid * 4 + 1] + reds[tid * 4 + 2] + reds[tid * 4 + 3];
        float q = redq[tid * 4] + redq[tid * 4 + 1] + redq[tid * 4 + 2] + redq[tid * 4 + 3];
        atomicAdd(&g_dsum[m0 + tid], (double)s);
        atomicAdd(&g_dsq[m0 + tid],  (double)q);
    }
}

// ---------------- BN finalize (last layer only) ----------------
__global__ void bn_final(const float* __restrict__ gamma, const float* __restrict__ beta, int F) {
    int f = threadIdx.x;
    if (f >= F) return;
    double mean = g_dsum[f] / (double)NN;
    double var  = g_dsq[f] / (double)NN - mean * mean;
    float sc = gamma[f] * rsqrtf((float)var + 1e-5f);
    g_bn_s[f] = sc;
    g_bn_t[f] = beta[f] - (float)mean * sc;
}

// ---------------- classifier ----------------
__global__ void classifier(const float* __restrict__ cw, const float* __restrict__ cb,
                           float* __restrict__ out) {
    const int b0   = blockIdx.x * 4;
    const int lane = threadIdx.x & 31;
    const int warp = threadIdx.x >> 5;

    float acc[4][10];
#pragma unroll
    for (int bb = 0; bb < 4; bb++)
#pragma unroll
        for (int o = 0; o < 10; o++) acc[bb][o] = 0.f;

    const int NF = 96 * GV;
    for (int f = threadIdx.x; f < NF; f += 256) {
        int c = f >> 10, v = f & (GV - 1);
        float sc = g_bn_s[c], sh = g_bn_t[c];
        float w[10];
#pragma unroll
        for (int o = 0; o < 10; o++) w[o] = cw[(size_t)o * NF + f];
#pragma unroll
        for (int bb = 0; bb < 4; bb++) {
            float y = g_act[(size_t)c * NN + (size_t)(b0 + bb) * GV + v];
            float h = fmaxf(fmaf(y, sc, sh), 0.f);
#pragma unroll
            for (int o = 0; o < 10; o++) acc[bb][o] = fmaf(h, w[o], acc[bb][o]);
        }
    }

    __shared__ float part[8][40];
#pragma unroll
    for (int bb = 0; bb < 4; bb++)
#pragma unroll
        for (int o = 0; o < 10; o++) {
            float vsum = acc[bb][o];
#pragma unroll
            for (int off = 16; off > 0; off >>= 1)
                vsum += __shfl_down_sync(0xffffffffu, vsum, off);
            if (lane == 0) part[warp][bb * 10 + o] = vsum;
        }
    __syncthreads();
    if (threadIdx.x < 40) {
        float ssum = 0.f;
#pragma unroll
        for (int wq = 0; wq < 8; wq++) ssum += part[wq][threadIdx.x];
        int bb = threadIdx.x / 10, o = threadIdx.x % 10;
        out[(b0 + bb) * 10 + o] = ssum + cb[o];
    }
}

// ---------------- launch ----------------
extern "C" void kernel_launch(void* const* d_in, const int* in_sizes, int n_in,
                              void* d_out, int out_size) {
    (void)out_size;
    const float* x = (const float*)d_in[0];
    const float* w[7];
    const float* gg[7];
    const float* bb[7];

    if (n_in >= 25 && in_sizes[3] == 96) {  // dict order (w,g,b per layer)
        for (int i = 0; i < 7; i++) {
            w[i]  = (const float*)d_in[2 + 3 * i];
            gg[i] = (const float*)d_in[3 + 3 * i];
            bb[i] = (const float*)d_in[4 + 3 * i];
        }
    } else {                                // signature order
        for (int i = 0; i < 7; i++) {
            w[i]  = (const float*)d_in[2 + i];
            gg[i] = (const float*)d_in[9 + i];
            bb[i] = (const float*)d_in[16 + i];
        }
    }
    const float* clf_w = (const float*)d_in[23];
    const float* clf_b = (const float*)d_in[24];

    static int smem_set = 0;
    if (!smem_set) {
        cudaFuncSetAttribute(gemm_mma, cudaFuncAttributeMaxDynamicSharedMemorySize, SMEM_GEMM);
        smem_set = 1;
    }

    const int CIN[7]  = {3, 96, 96, 96, 192, 192, 192};
    const int FOUT[7] = {96, 96, 96, 192, 192, 192, 96};

    for (int l = 0; l < 7; l++) {
        const int C = CIN[l], F = FOUT[l], CK = C * KORD;

        wsplit_bn<<<(F * CKP + 255) / 256, 256>>>(
            w[l], F, CK,
            l ? gg[l - 1] : nullptr, l ? bb[l - 1] : nullptr,
            l ? FOUT[l - 1] : 0, l ? 1 : 0);

        cheb_expand<<<dim3(C, GB), 256>>>(x, C, l == 0 ? 1 : 0);

        dim3 grid(F / 96, NN / 128);
        gemm_mma<<<grid, 256, SMEM_GEMM>>>(F, CK);
    }

    bn_final<<<1, 192>>>(gg[6], bb[6], 96);
    classifier<<<32, 256>>>(clf_w, clf_b, (float*)d_out);
}